// round 15
// baseline (speedup 1.0000x reference)
#include <cuda_runtime.h>
#include <cuda_fp16.h>
#include <cstdint>

// CMPModel density matrix via fp16 mma.sync m16n8k16 (f32 accum), sm_103.
// V=50000, D=256, S=128, B=64.
//
// R[k,d]=word_emb[q[k],d], I[k,d]=cmp_emb[q[k],d]*pos[k]
//   real[d,e] = sum_k w[k]( R[k,d]R[k,e] + I[k,d]I[k,e] )
//   imag[d,e] = sum_k w[k]( I[k,d]R[k,e] - R[k,d]I[k,e] )
//
// CTA = (e-half, d-half, batch), 256 CTAs.  ALL 4 chunk stages resident
// (128KB smem).  TWO passes: real then imag (acc = 32 regs per pass) —
// the freed registers let gather batch ALL 8 LDG.128 into registers
// (gather_load) BEFORE compute of the previous chunk, with the convert+
// STS (gather_store) after: LDG latency hides under ~1.5K cyc of MMA.
// Imag pass runs entirely from resident smem: zero loads, zero barriers.
// Tiles stored unscaled (R, pos*I); w applied to B fragments in compute
// (mul.f16x2, w-pair table).  Diagonal CTAs load only A tiles (half LDG).
// Fragments via ldmatrix.x4.trans ([k][128feat], 256B rows, ^(k&7)
// swizzle).  Imag minus sign: negate aR fragment (XOR 0x80008000).

#define D_DIM 256
#define S_LEN 128
#define B_DIM 64
#define KC    32

#define STAGE_BYTES 32768                   // AR/AI/BR/BI per 32 tokens
#define SMEM_BYTES  (4 * STAGE_BYTES)       // 128KB: whole S resident

#define AR_OFF 0
#define AI_OFF 8192
#define BR_OFF 16384
#define BI_OFF 24576

__device__ __forceinline__ void ldmx4t(uint32_t* r, uint32_t addr) {
    asm("ldmatrix.sync.aligned.m8n8.x4.trans.shared.b16 {%0,%1,%2,%3}, [%4];"
        : "=r"(r[0]), "=r"(r[1]), "=r"(r[2]), "=r"(r[3]) : "r"(addr));
}

__device__ __forceinline__ void mma16(float* c, const uint32_t* a,
                                      const uint32_t* b) {
    asm("mma.sync.aligned.m16n8k16.row.col.f32.f16.f16.f32 "
        "{%0,%1,%2,%3}, {%4,%5,%6,%7}, {%8,%9}, {%0,%1,%2,%3};"
        : "+f"(c[0]), "+f"(c[1]), "+f"(c[2]), "+f"(c[3])
        : "r"(a[0]), "r"(a[1]), "r"(a[2]), "r"(a[3]), "r"(b[0]), "r"(b[1]));
}

// pack two f32 into f16x2 with ONE cvt instruction (lo=x, hi=y)
__device__ __forceinline__ uint32_t h2(float x, float y) {
    uint32_t r;
    asm("cvt.rn.f16x2.f32 %0, %1, %2;" : "=r"(r) : "f"(y), "f"(x));
    return r;
}

__device__ __forceinline__ uint32_t hmul2u(uint32_t a, uint32_t b) {
    uint32_t d;
    asm("mul.f16x2 %0, %1, %2;" : "=r"(d) : "r"(a), "r"(b));
    return d;
}

__global__ void __launch_bounds__(512, 1)
cmp_fp16g_kernel(const int*   __restrict__ questions,
                 const float* __restrict__ qpos,
                 const float* __restrict__ wemb,
                 const float* __restrict__ cemb,
                 const float* __restrict__ wq,
                 float*       __restrict__ out)
{
    extern __shared__ char sm[];
    __shared__ int      sq[S_LEN];
    __shared__ float    sp[S_LEN];
    __shared__ uint32_t w2s[S_LEN / 2];

    const int tid  = threadIdx.x;
    const int wid  = tid >> 5;
    const int lane = tid & 31;
    const int et   = blockIdx.x;
    const int dt   = blockIdx.y;
    const int b    = blockIdx.z;
    const bool diag = (et == dt);

    if (tid < S_LEN) {
        sq[tid] = questions[b * S_LEN + tid];
        sp[tid] = qpos[b * S_LEN + tid];
    }
    if (tid < S_LEN / 2) {
        w2s[tid] = h2(wq[2 * tid], wq[2 * tid + 1]);
    }
    __syncthreads();

    const uint32_t smem_u = (uint32_t)__cvta_generic_to_shared(sm);

    const int mr = wid >> 2;       // d block (32 rows), 0..3
    const int nc = wid & 3;        // e block (32 cols), 0..3

    // ldmatrix per-lane address components
    const int xorv  = lane & 7;
    const int krowA = (lane & 7) | ((lane & 16) >> 1);   // A: m8-sel in bit3
    const int aCh   = (lane >> 3) & 1;
    const int krowB = (lane & 7) | (lane & 8);           // B: n8-sel in bit4
    const int bCh   = (lane >> 4) & 1;

    const uint32_t aBase = (uint32_t)krowA * 256 +
        (uint32_t)(((mr * 4 + aCh) ^ xorv) * 16);
    const uint32_t bBase = (uint32_t)krowB * 256 +
        (uint32_t)(((nc * 4 + bCh) ^ xorv) * 16);

    const int wsel = lane & 3;

    // B fragments come from the A tiles on diagonal CTAs (same feat half)
    const uint32_t bROff = diag ? AR_OFF : BR_OFF;
    const uint32_t bIOff = diag ? AI_OFF : BI_OFF;
    const int niter = diag ? 2 : 4;

    float4 rv[4], cv[4];

    // ---- gather phase 1: batch ALL LDGs into registers (MLP=8) ----
    auto gather_load = [&](int g) {
#pragma unroll
        for (int i = 0; i < 4; ++i) {
            if (i >= niter) break;
            const int t    = tid + i * 512;
            const int half = t >> 10;
            const int k    = (t >> 5) & 31;
            const int f4   = t & 31;
            const int fofs = (half ? et : dt) * 128 + f4 * 4;
            const int q    = sq[g * KC + k];
            rv[i] = *(const float4*)(wemb + (size_t)q * D_DIM + fofs);
            cv[i] = *(const float4*)(cemb + (size_t)q * D_DIM + fofs);
        }
    };

    // ---- gather phase 2: convert + STS ----
    auto gather_store = [&](int g) {
        const uint32_t stg = smem_u + (uint32_t)g * STAGE_BYTES;
#pragma unroll
        for (int i = 0; i < 4; ++i) {
            if (i >= niter) break;
            const int t    = tid + i * 512;
            const int half = t >> 10;
            const int k    = (t >> 5) & 31;
            const int f4   = t & 31;
            const float pp = sp[g * KC + k];

            const uint32_t dst = stg + (half ? BR_OFF : AR_OFF) +
                (uint32_t)k * 256 +
                (uint32_t)(((f4 >> 1) ^ (k & 7)) * 16 + (f4 & 1) * 8);

            uint2 vR = make_uint2(h2(rv[i].x, rv[i].y), h2(rv[i].z, rv[i].w));
            uint2 vI = make_uint2(h2(cv[i].x * pp, cv[i].y * pp),
                                  h2(cv[i].z * pp, cv[i].w * pp));
            asm volatile("st.shared.v2.b32 [%0], {%1,%2};"
                         :: "r"(dst), "r"(vR.x), "r"(vR.y));
            asm volatile("st.shared.v2.b32 [%0], {%1,%2};"
                         :: "r"(dst + 8192), "r"(vI.x), "r"(vI.y));
        }
    };

    float acc[2][4][4];
    auto clear_acc = [&]() {
#pragma unroll
        for (int i = 0; i < 2; i++)
#pragma unroll
            for (int j = 0; j < 4; j++)
#pragma unroll
                for (int q = 0; q < 4; q++) acc[i][j][q] = 0.f;
    };

    // ---- compute one chunk; pass 0: real, pass 1: imag ----
    auto compute = [&](int g, int pass) {
        const uint32_t stg = smem_u + (uint32_t)g * STAGE_BYTES;
#pragma unroll
        for (int kg = 0; kg < 2; ++kg) {
            const uint32_t kofs = (uint32_t)kg * 4096;
            const int wbase = (g * 2 + kg) * 8;
            const uint32_t w2lo = w2s[wbase + wsel];
            const uint32_t w2hi = w2s[wbase + 4 + wsel];

            uint32_t bR[8], bI[8];
#pragma unroll
            for (int ntp = 0; ntp < 2; ++ntp) {
                const uint32_t badj = bBase ^ (uint32_t)(ntp * 32);
                uint32_t tR[4], tI[4];
                ldmx4t(tR, stg + bROff + kofs + badj);
                ldmx4t(tI, stg + bIOff + kofs + badj);
#pragma unroll
                for (int j = 0; j < 4; ++j) {
                    const uint32_t wv = (j & 1) ? w2hi : w2lo;
                    bR[4 * ntp + j] = hmul2u(tR[j], wv);
                    bI[4 * ntp + j] = hmul2u(tI[j], wv);
                }
            }

#pragma unroll
            for (int mt = 0; mt < 2; ++mt) {
                const uint32_t aadj = aBase ^ (uint32_t)(mt * 32);
                uint32_t a1[4], a2[4];
                ldmx4t(a1, stg + AR_OFF + kofs + aadj);   // R
                ldmx4t(a2, stg + AI_OFF + kofs + aadj);   // I
                if (pass) {
                    // imag: aI*bR + (-aR)*bI  -> a1 := -R, swap roles
#pragma unroll
                    for (int j = 0; j < 4; ++j) a1[j] ^= 0x80008000u;
#pragma unroll
                    for (int nt = 0; nt < 4; ++nt) {
                        const int bi = (nt >> 1) * 4 + (nt & 1) * 2;
                        mma16(acc[mt][nt], a2, bR + bi);
                    }
#pragma unroll
                    for (int nt = 0; nt < 4; ++nt) {
                        const int bi = (nt >> 1) * 4 + (nt & 1) * 2;
                        mma16(acc[mt][nt], a1, bI + bi);
                    }
                } else {
                    // real: aR*bR + aI*bI
#pragma unroll
                    for (int nt = 0; nt < 4; ++nt) {
                        const int bi = (nt >> 1) * 4 + (nt & 1) * 2;
                        mma16(acc[mt][nt], a1, bR + bi);
                    }
#pragma unroll
                    for (int nt = 0; nt < 4; ++nt) {
                        const int bi = (nt >> 1) * 4 + (nt & 1) * 2;
                        mma16(acc[mt][nt], a2, bI + bi);
                    }
                }
            }
        }
    };

    const int r = lane >> 2;
    const int c = lane & 3;
    float* oRe = out + (size_t)b * D_DIM * D_DIM;
    float* oIm = oRe + (size_t)B_DIM * D_DIM * D_DIM;

    auto epilogue = [&](float* ob) {
#pragma unroll
        for (int mt = 0; mt < 2; ++mt) {
            const int d = dt * 128 + mr * 32 + mt * 16 + r;
#pragma unroll
            for (int nt = 0; nt < 4; ++nt) {
                const int e = et * 128 + nc * 32 + nt * 8 + 2 * c;
                *(float2*)(ob + (size_t)d * D_DIM + e) =
                    make_float2(acc[mt][nt][0], acc[mt][nt][1]);
                *(float2*)(ob + (size_t)(d + 8) * D_DIM + e) =
                    make_float2(acc[mt][nt][2], acc[mt][nt][3]);
            }
        }
    };

    // ================= pass 0: real, with pipelined gather ================
    clear_acc();
    gather_load(0);
    gather_store(0);
    __syncthreads();
#pragma unroll
    for (int g = 0; g < 4; ++g) {
        if (g < 3) gather_load(g + 1);    // LDGs in flight during compute
        compute(g, 0);
        if (g < 3) {
            gather_store(g + 1);          // loads have landed by now
            __syncthreads();
        }
    }
    epilogue(oRe);

    // ================= pass 1: imag, pure MMA from resident smem ==========
    clear_acc();
#pragma unroll
    for (int g = 0; g < 4; ++g) compute(g, 1);
    epilogue(oIm);
}

extern "C" void kernel_launch(void* const* d_in, const int* in_sizes, int n_in,
                              void* d_out, int out_size) {
    const int*   questions = (const int*)d_in[0];
    const float* qpos      = (const float*)d_in[1];
    const float* wemb      = (const float*)d_in[2];
    const float* cemb      = (const float*)d_in[3];
    const float* wq        = (const float*)d_in[4];
    float*       out       = (float*)d_out;

    cudaFuncSetAttribute(cmp_fp16g_kernel,
                         cudaFuncAttributeMaxDynamicSharedMemorySize, SMEM_BYTES);

    dim3 grid(2 /*e-half*/, 2 /*d-half*/, B_DIM);
    cmp_fp16g_kernel<<<grid, 512, SMEM_BYTES>>>(questions, qpos, wemb, cemb,
                                                wq, out);
}

// round 16
// speedup vs baseline: 1.7661x; 1.7661x over previous
#include <cuda_runtime.h>
#include <cuda_fp16.h>
#include <cstdint>

// CMPModel density matrix, two-kernel scheme, sm_103.
// V=50000, D=256, S=128, B=64.
//
// R[k,d]=word_emb[q[k],d], I[k,d]=cmp_emb[q[k],d]*pos[k]
//   real[d,e] = sum_k w[k]( R[k,d]R[k,e] + I[k,d]I[k,e] )
//   imag[d,e] = sum_k w[k]( I[k,d]R[k,e] - R[k,d]I[k,e] )
//
// Kernel 1 (pack): gather+convert each (b,s) row ONCE into fp16 buffers
//   packR/packI [8192][256] (device globals).  Removes the chip-wide 4x
//   gather duplication and all cvt work from the GEMM.
// Kernel 2 (GEMM): R14-validated mma.sync m16n8k16 quadrant kernel, but
//   tiles arrive via cp.async.cg 16B copies (no registers, no cvt, no
//   LDG scoreboard chains).  4 stages = 4 commit groups issued up-front;
//   wait_group N + barrier gates each compute chunk.  w applied to B
//   fragments via mul.f16x2; diag CTAs copy only A tiles (half traffic).

#define D_DIM 256
#define S_LEN 128
#define B_DIM 64
#define KC    32
#define NTOK  (B_DIM * S_LEN)               // 8192

__device__ uint32_t g_packR[NTOK * 128];    // [tok][256 fp16] as uint32 pairs
__device__ uint32_t g_packI[NTOK * 128];

#define STAGE_BYTES 32768                   // AR/AI/BR/BI (8KB each) / 32 tok
#define SMEM_BYTES  (4 * STAGE_BYTES)       // 128KB: whole S resident

#define AR_OFF 0
#define AI_OFF 8192
#define BR_OFF 16384
#define BI_OFF 24576

__device__ __forceinline__ void ldmx4t(uint32_t* r, uint32_t addr) {
    asm("ldmatrix.sync.aligned.m8n8.x4.trans.shared.b16 {%0,%1,%2,%3}, [%4];"
        : "=r"(r[0]), "=r"(r[1]), "=r"(r[2]), "=r"(r[3]) : "r"(addr));
}

__device__ __forceinline__ void mma16(float* c, const uint32_t* a,
                                      const uint32_t* b) {
    asm("mma.sync.aligned.m16n8k16.row.col.f32.f16.f16.f32 "
        "{%0,%1,%2,%3}, {%4,%5,%6,%7}, {%8,%9}, {%0,%1,%2,%3};"
        : "+f"(c[0]), "+f"(c[1]), "+f"(c[2]), "+f"(c[3])
        : "r"(a[0]), "r"(a[1]), "r"(a[2]), "r"(a[3]), "r"(b[0]), "r"(b[1]));
}

__device__ __forceinline__ uint32_t h2(float x, float y) {
    uint32_t r;
    asm("cvt.rn.f16x2.f32 %0, %1, %2;" : "=r"(r) : "f"(y), "f"(x));
    return r;
}

__device__ __forceinline__ uint32_t hmul2u(uint32_t a, uint32_t b) {
    uint32_t d;
    asm("mul.f16x2 %0, %1, %2;" : "=r"(d) : "r"(a), "r"(b));
    return d;
}

__device__ __forceinline__ void cpa16(uint32_t dst, const void* src) {
    asm volatile("cp.async.cg.shared.global [%0], [%1], 16;"
                 :: "r"(dst), "l"(src));
}

// ======================= kernel 1: pack =======================
__global__ void __launch_bounds__(512)
cmp_pack_kernel(const int*   __restrict__ questions,
                const float* __restrict__ qpos,
                const float* __restrict__ wemb,
                const float* __restrict__ cemb)
{
    const int idx0 = blockIdx.x * 512 + threadIdx.x;
#pragma unroll
    for (int i = 0; i < 4; ++i) {
        const int idx = idx0 + i * 131072;      // 524288 tasks total
        const int tok = idx >> 6;               // 0..8191
        const int f4  = idx & 63;               // float4 index over 256 feats
        const int   q  = questions[tok];
        const float pp = qpos[tok];
        const float4 rv = *(const float4*)(wemb + (size_t)q * D_DIM + f4 * 4);
        const float4 cv = *(const float4*)(cemb + (size_t)q * D_DIM + f4 * 4);
        uint2 vR = make_uint2(h2(rv.x, rv.y), h2(rv.z, rv.w));
        uint2 vI = make_uint2(h2(cv.x * pp, cv.y * pp),
                              h2(cv.z * pp, cv.w * pp));
        *(uint2*)(g_packR + (size_t)tok * 128 + f4 * 2) = vR;
        *(uint2*)(g_packI + (size_t)tok * 128 + f4 * 2) = vI;
    }
}

// ======================= kernel 2: GEMM =======================
__global__ void __launch_bounds__(512, 1)
cmp_gemm_kernel(const float* __restrict__ wq,
                float*       __restrict__ out)
{
    extern __shared__ char sm[];
    __shared__ uint32_t w2s[S_LEN / 2];

    const int tid  = threadIdx.x;
    const int wid  = tid >> 5;
    const int lane = tid & 31;
    const int et   = blockIdx.x;
    const int dt   = blockIdx.y;
    const int b    = blockIdx.z;
    const bool diag = (et == dt);

    if (tid < S_LEN / 2) {
        w2s[tid] = h2(wq[2 * tid], wq[2 * tid + 1]);
    }
    __syncthreads();

    const uint32_t smem_u = (uint32_t)__cvta_generic_to_shared(sm);

    // ---- issue all cp.async stages up-front (4 commit groups) ----
    {
        const int niter = diag ? 1 : 2;
        for (int g = 0; g < 4; ++g) {
            const uint32_t stg = smem_u + (uint32_t)g * STAGE_BYTES;
#pragma unroll
            for (int i = 0; i < 2; ++i) {
                if (i >= niter) break;
                const int t    = tid + i * 512;      // 0..1023
                const int half = t >> 9;             // 0: A (dt), 1: B (et)
                const int u    = t & 511;
                const int k    = u >> 4;             // 0..31
                const int f8   = u & 15;             // 16B chunk (8 feats)

                const int tok  = b * S_LEN + g * KC + k;
                const int fcol = (half ? et : dt) * 64 + f8 * 4;  // uint idx
                const uint32_t dst = stg + (half ? BR_OFF : AR_OFF) +
                    (uint32_t)k * 256 + (uint32_t)((f8 ^ (k & 7)) << 4);
                cpa16(dst,        g_packR + (size_t)tok * 128 + fcol);
                cpa16(dst + 8192, g_packI + (size_t)tok * 128 + fcol);
            }
            asm volatile("cp.async.commit_group;");
        }
    }

    const int mr = wid >> 2;       // d block (32 rows), 0..3
    const int nc = wid & 3;        // e block (32 cols), 0..3

    float accRe[2][4][4];
    float accIm[2][4][4];
#pragma unroll
    for (int i = 0; i < 2; i++)
#pragma unroll
        for (int j = 0; j < 4; j++)
#pragma unroll
            for (int q = 0; q < 4; q++) { accRe[i][j][q] = 0.f; accIm[i][j][q] = 0.f; }

    // ldmatrix per-lane address components
    const int xorv  = lane & 7;
    const int krowA = (lane & 7) | ((lane & 16) >> 1);   // A: m8-sel in bit3
    const int aCh   = (lane >> 3) & 1;
    const int krowB = (lane & 7) | (lane & 8);           // B: n8-sel in bit4
    const int bCh   = (lane >> 4) & 1;

    const uint32_t aBase = (uint32_t)krowA * 256 +
        (uint32_t)(((mr * 4 + aCh) ^ xorv) * 16);
    const uint32_t bBase = (uint32_t)krowB * 256 +
        (uint32_t)(((nc * 4 + bCh) ^ xorv) * 16);

    const int wsel = lane & 3;

    const uint32_t bROff = diag ? AR_OFF : BR_OFF;
    const uint32_t bIOff = diag ? AI_OFF : BI_OFF;

    // ---- compute one chunk (R14-validated) ----
    auto compute = [&](int g) {
        const uint32_t stg = smem_u + (uint32_t)g * STAGE_BYTES;
#pragma unroll
        for (int kg = 0; kg < 2; ++kg) {
            const uint32_t kofs = (uint32_t)kg * 4096;
            const int wbase = (g * 2 + kg) * 8;
            const uint32_t w2lo = w2s[wbase + wsel];
            const uint32_t w2hi = w2s[wbase + 4 + wsel];

            uint32_t bR[8], bI[8];
#pragma unroll
            for (int ntp = 0; ntp < 2; ++ntp) {
                const uint32_t badj = bBase ^ (uint32_t)(ntp * 32);
                uint32_t tR[4], tI[4];
                ldmx4t(tR, stg + bROff + kofs + badj);
                ldmx4t(tI, stg + bIOff + kofs + badj);
#pragma unroll
                for (int j = 0; j < 4; ++j) {
                    const uint32_t wv = (j & 1) ? w2hi : w2lo;
                    bR[4 * ntp + j] = hmul2u(tR[j], wv);
                    bI[4 * ntp + j] = hmul2u(tI[j], wv);
                }
            }

#pragma unroll
            for (int mt = 0; mt < 2; ++mt) {
                const uint32_t aadj = aBase ^ (uint32_t)(mt * 32);
                uint32_t aR[4], aI[4], aN[4];
                ldmx4t(aR, stg + AR_OFF + kofs + aadj);
                ldmx4t(aI, stg + AI_OFF + kofs + aadj);
#pragma unroll
                for (int j = 0; j < 4; ++j) aN[j] = aR[j] ^ 0x80008000u;

#pragma unroll
                for (int nt = 0; nt < 4; ++nt) {
                    const int bi = (nt >> 1) * 4 + (nt & 1) * 2;
                    mma16(accRe[mt][nt], aR, bR + bi);
                }
#pragma unroll
                for (int nt = 0; nt < 4; ++nt) {
                    const int bi = (nt >> 1) * 4 + (nt & 1) * 2;
                    mma16(accRe[mt][nt], aI, bI + bi);
                }
#pragma unroll
                for (int nt = 0; nt < 4; ++nt) {
                    const int bi = (nt >> 1) * 4 + (nt & 1) * 2;
                    mma16(accIm[mt][nt], aI, bR + bi);
                }
#pragma unroll
                for (int nt = 0; nt < 4; ++nt) {
                    const int bi = (nt >> 1) * 4 + (nt & 1) * 2;
                    mma16(accIm[mt][nt], aN, bI + bi);
                }
            }
        }
    };

    asm volatile("cp.async.wait_group 3;" ::: "memory");
    __syncthreads();
    compute(0);
    asm volatile("cp.async.wait_group 2;" ::: "memory");
    __syncthreads();
    compute(1);
    asm volatile("cp.async.wait_group 1;" ::: "memory");
    __syncthreads();
    compute(2);
    asm volatile("cp.async.wait_group 0;" ::: "memory");
    __syncthreads();
    compute(3);

    // ---- epilogue ----
    const int r = lane >> 2;
    const int c = lane & 3;
    float* oRe = out + (size_t)b * D_DIM * D_DIM;
    float* oIm = oRe + (size_t)B_DIM * D_DIM * D_DIM;
#pragma unroll
    for (int mt = 0; mt < 2; ++mt) {
        const int d = dt * 128 + mr * 32 + mt * 16 + r;
#pragma unroll
        for (int nt = 0; nt < 4; ++nt) {
            const int e = et * 128 + nc * 32 + nt * 8 + 2 * c;
            *(float2*)(oRe + (size_t)d * D_DIM + e) =
                make_float2(accRe[mt][nt][0], accRe[mt][nt][1]);
            *(float2*)(oRe + (size_t)(d + 8) * D_DIM + e) =
                make_float2(accRe[mt][nt][2], accRe[mt][nt][3]);
            *(float2*)(oIm + (size_t)d * D_DIM + e) =
                make_float2(accIm[mt][nt][0], accIm[mt][nt][1]);
            *(float2*)(oIm + (size_t)(d + 8) * D_DIM + e) =
                make_float2(accIm[mt][nt][2], accIm[mt][nt][3]);
        }
    }
}

extern "C" void kernel_launch(void* const* d_in, const int* in_sizes, int n_in,
                              void* d_out, int out_size) {
    const int*   questions = (const int*)d_in[0];
    const float* qpos      = (const float*)d_in[1];
    const float* wemb      = (const float*)d_in[2];
    const float* cemb      = (const float*)d_in[3];
    const float* wq        = (const float*)d_in[4];
    float*       out       = (float*)d_out;

    cudaFuncSetAttribute(cmp_gemm_kernel,
                         cudaFuncAttributeMaxDynamicSharedMemorySize, SMEM_BYTES);

    cmp_pack_kernel<<<256, 512>>>(questions, qpos, wemb, cemb);

    dim3 grid(2 /*e-half*/, 2 /*d-half*/, B_DIM);
    cmp_gemm_kernel<<<grid, 512, SMEM_BYTES>>>(wq, out);
}